// round 16
// baseline (speedup 1.0000x reference)
#include <cuda_runtime.h>
#include <cuda_bf16.h>
#include <math.h>

// ---------------------------------------------------------------------------
// Problem constants
// ---------------------------------------------------------------------------
#define T_MAX 4096
#define H_DIM 2048
#define OUT_DIM 10
#define NCTA 148
#define SCAN_THREADS 512
#define EPS 1e-6f

typedef unsigned long long ull;

// packed fp32x2 helpers (PTX ISA 8.7+, sm_100+)
__device__ __forceinline__ void fma2(ull& acc, ull a, ull b) {
    asm("fma.rn.f32x2 %0, %1, %2, %0;" : "+l"(acc) : "l"(a), "l"(b));
}
__device__ __forceinline__ ull pack2(float x, float y) {
    ull r; asm("mov.b64 %0, {%1, %2};" : "=l"(r) : "f"(x), "f"(y)); return r;
}
__device__ __forceinline__ float2 unpack2(ull p) {
    float2 f; asm("mov.b64 {%0, %1}, %2;" : "=f"(f.x), "=f"(f.y) : "l"(p)); return f;
}

// tf32 helpers
__device__ __forceinline__ float totf32(float x) {
    float r; asm("cvt.rna.tf32.f32 %0, %1;" : "=f"(r) : "f"(x)); return r;
}
__device__ __forceinline__ void mma_tf32(float* c, const float* a, const float* b) {
    asm("mma.sync.aligned.m16n8k8.row.col.f32.tf32.tf32.f32 "
        "{%0,%1,%2,%3}, {%4,%5,%6,%7}, {%8,%9}, {%0,%1,%2,%3};"
        : "+f"(c[0]), "+f"(c[1]), "+f"(c[2]), "+f"(c[3])
        : "f"(a[0]), "f"(a[1]), "f"(a[2]), "f"(a[3]), "f"(b[0]), "f"(b[1]));
}

// tagged dataflow word: (epoch << 32) | float_bits. Relaxed gpu-scope ld/st;
// the tag rides with the value, so value visibility needs NO fences.
__device__ __forceinline__ void st_tagged(ull* p, ull v) {
    asm volatile("st.relaxed.gpu.global.u64 [%0], %1;" :: "l"(p), "l"(v) : "memory");
}
__device__ __forceinline__ ull ld_tagged(const ull* p) {
    ull v;
    asm volatile("ld.relaxed.gpu.global.u64 %0, [%1];" : "=l"(v) : "l"(p) : "memory");
    return v;
}

// scratch (device globals: allocation-free)
__device__ float g_xf[T_MAX * H_DIM];   // x @ W_f + b_f
__device__ float g_xh[T_MAX * H_DIM];   // x @ W_h + b_h
__device__ float g_h [T_MAX * H_DIM];   // scan output
__device__ float g_hn[T_MAX * H_DIM];   // layernorm output (layer 0)
__device__ ull   g_hx[2 * H_DIM];       // tagged h exchange (2-deep)
__device__ int   g_ctr[T_MAX * 32];     // split "ready" counters (32/step)

// ---------------------------------------------------------------------------
// TF32 tensor-core GEMM with bias, fused f/h pair (blockIdx.z selects).
// (unchanged: 154 TF/s measured, 0.45 ms/launch)
// ---------------------------------------------------------------------------
#define GBK 32
#define AS_STR 36
#define BS_STR 136

__global__ __launch_bounds__(256) void tf32_gemm_bias2_kernel(
    const float* __restrict__ A,
    const float* __restrict__ Bf, const float* __restrict__ biasf, float* __restrict__ Cf,
    const float* __restrict__ Bh, const float* __restrict__ biash, float* __restrict__ Ch,
    int M, int N, int K)
{
    __shared__ float As[128 * AS_STR];
    __shared__ float Bs[GBK * BS_STR];

    const float* B    = blockIdx.z ? Bh : Bf;
    const float* bias = blockIdx.z ? biash : biasf;
    float*       C    = blockIdx.z ? Ch : Cf;

    const int tid  = threadIdx.x;
    const int warp = tid >> 5;
    const int lane = tid & 31;
    const int g    = lane >> 2;
    const int tg   = lane & 3;

    const int wm = (warp >> 2) * 64;
    const int wn = (warp & 3) * 32;

    const int ar  = tid >> 3;
    const int ac4 = (tid & 7) * 4;
    const int br  = tid >> 5;
    const int bc4 = (tid & 31) * 4;

    float acc[4][4][4];
    #pragma unroll
    for (int mt = 0; mt < 4; mt++)
        #pragma unroll
        for (int nt = 0; nt < 4; nt++)
            #pragma unroll
            for (int r = 0; r < 4; r++) acc[mt][nt][r] = 0.f;

    const float* Ap = A + (size_t)(blockIdx.y * 128) * K;
    const float* Bp = B + blockIdx.x * 128;

    for (int kt = 0; kt < K; kt += GBK) {
        float4 a4[4], b4[4];
        #pragma unroll
        for (int i = 0; i < 4; i++)
            a4[i] = *(const float4*)(Ap + (size_t)(ar + 32 * i) * K + kt + ac4);
        #pragma unroll
        for (int i = 0; i < 4; i++)
            b4[i] = *(const float4*)(Bp + (size_t)(kt + br + 8 * i) * N + bc4);
        #pragma unroll
        for (int i = 0; i < 4; i++) {
            a4[i].x = totf32(a4[i].x); a4[i].y = totf32(a4[i].y);
            a4[i].z = totf32(a4[i].z); a4[i].w = totf32(a4[i].w);
            b4[i].x = totf32(b4[i].x); b4[i].y = totf32(b4[i].y);
            b4[i].z = totf32(b4[i].z); b4[i].w = totf32(b4[i].w);
        }
        __syncthreads();
        #pragma unroll
        for (int i = 0; i < 4; i++)
            *(float4*)&As[(ar + 32 * i) * AS_STR + ac4] = a4[i];
        #pragma unroll
        for (int i = 0; i < 4; i++)
            *(float4*)&Bs[(br + 8 * i) * BS_STR + bc4] = b4[i];
        __syncthreads();

        #pragma unroll
        for (int ks = 0; ks < 4; ks++) {
            const int kk = ks * 8;
            float af[4][4], bf[4][2];
            #pragma unroll
            for (int mt = 0; mt < 4; mt++) {
                const int m0 = wm + mt * 16;
                af[mt][0] = As[(m0 + g)     * AS_STR + kk + tg];
                af[mt][1] = As[(m0 + g + 8) * AS_STR + kk + tg];
                af[mt][2] = As[(m0 + g)     * AS_STR + kk + tg + 4];
                af[mt][3] = As[(m0 + g + 8) * AS_STR + kk + tg + 4];
            }
            #pragma unroll
            for (int nt = 0; nt < 4; nt++) {
                const int n0 = wn + nt * 8;
                bf[nt][0] = Bs[(kk + tg)     * BS_STR + n0 + g];
                bf[nt][1] = Bs[(kk + tg + 4) * BS_STR + n0 + g];
            }
            #pragma unroll
            for (int mt = 0; mt < 4; mt++)
                #pragma unroll
                for (int nt = 0; nt < 4; nt++)
                    mma_tf32(acc[mt][nt], af[mt], bf[nt]);
        }
    }

    #pragma unroll
    for (int mt = 0; mt < 4; mt++) {
        const int row0 = blockIdx.y * 128 + wm + mt * 16 + g;
        const int row1 = row0 + 8;
        #pragma unroll
        for (int nt = 0; nt < 4; nt++) {
            const int col = blockIdx.x * 128 + wn + nt * 8 + 2 * tg;
            const float b0 = bias[col], b1 = bias[col + 1];
            float2 v0, v1;
            v0.x = acc[mt][nt][0] + b0; v0.y = acc[mt][nt][1] + b1;
            v1.x = acc[mt][nt][2] + b0; v1.y = acc[mt][nt][3] + b1;
            *(float2*)(C + (size_t)row0 * N + col) = v0;
            *(float2*)(C + (size_t)row1 * N + col) = v1;
        }
    }
}

// ---------------------------------------------------------------------------
// Persistent JANET scan — staging OVERLAPPED into phase 3.
// 148 CTAs x 512 threads (16 warps), 1 CTA/SM (smem-pinned, single wave).
//
// Step t (hsm holds h_{t-1}, staged during the previous phase 3):
//   1. all 16 warps: packed f32x2 partial dot from hsm -> part[]
//   2. __syncthreads (A)
//   3. phase 3 (all bounded between sync A and sync B):
//        warp 0 : reduce partials, gate, __stcg Hout, st_tagged h_t
//        warp 1 : atomicAdd ctr[t*32 + (b&31)]  (advisory arrive)
//        warp 2 : poll the 32 split counter words vs quota (detect)
//        warps 3-15: tag-poll-STAGE h_t chunks into hsm for step t+1
//                    (warp w -> chunk w; warps 3,4,5 also chunks 0,1,2).
//                    Publishes happen in this same window chip-wide, so
//                    polls hit in ~1-2 sweeps; window is HARD-BOUNDED by
//                    the block syncs (no cross-step free-running).
//   4. __syncthreads (B) -> next step dots immediately from smem.
// Slot safety: publish h_{t+1} happens after detect(t) => all CTAs passed
// sync B(t-1) => finished staging reads of h_{t-1} (slot (t+1)&1). No
// fences: values self-validate via epoch tags in the same 64-bit word.
// ---------------------------------------------------------------------------
__global__ __launch_bounds__(SCAN_THREADS, 1) void janet_scan_kernel(
    const float* __restrict__ Uf, const float* __restrict__ Uh,
    const float* __restrict__ xf, const float* __restrict__ xh,
    float* __restrict__ Hout, const float* __restrict__ prelu_a,
    ull* __restrict__ hx, int* __restrict__ ctr, unsigned ebase, int T)
{
    extern __shared__ float smem[];
    const int H = H_DIM;
    ulonglong2* ws2 = (ulonglong2*)smem;      // 16 warps * 8 * 32 * 16B = 64KB
    float* hsm  = smem + (64 * 1024 / 4);     // 2048 floats (8KB)
    float* part = hsm + H;                    // 512 floats (2KB)

    const int b = blockIdx.x;
    const int c0 = (b * H) / NCTA;
    const int c1 = ((b + 1) * H) / NCTA;
    const int np = c1 - c0;          // 13 or 14 column pairs
    const int nd = 2 * np;

    const int tid  = threadIdx.x;
    const int lane = tid & 31;
    const int warp = tid >> 5;
    const float a = *prelu_a;

    // ---- load this lane's weights: 96 floats in regs + 32 in smem ----
    const bool valid = lane < nd;
    const int col = c0 + (lane < np ? lane : (valid ? lane - np : 0));
    const float* U = (lane < np) ? Uf : Uh;
    const int kbase = warp * 128;

    ull wr[48];
    #pragma unroll
    for (int i = 0; i < 48; i++) {
        const float w0 = valid ? U[(size_t)(kbase + 2 * i + 0) * H + col] : 0.f;
        const float w1 = valid ? U[(size_t)(kbase + 2 * i + 1) * H + col] : 0.f;
        wr[i] = pack2(w0, w1);
    }
    #pragma unroll
    for (int jp = 0; jp < 8; jp++) {
        const int kk = kbase + 96 + 4 * jp;
        const float w0 = valid ? U[(size_t)(kk + 0) * H + col] : 0.f;
        const float w1 = valid ? U[(size_t)(kk + 1) * H + col] : 0.f;
        const float w2 = valid ? U[(size_t)(kk + 2) * H + col] : 0.f;
        const float w3 = valid ? U[(size_t)(kk + 3) * H + col] : 0.f;
        ulonglong2 wv; wv.x = pack2(w0, w1); wv.y = pack2(w2, w3);
        ws2[warp * 256 + jp * 32 + lane] = wv;
    }

    // per-dot thread state (warp 0, lane < np drives the gate math)
    float hprev = 0.f, xf_c = 0.f, xh_c = 0.f;
    const int myc = c0 + lane;
    if (warp == 0 && lane < np) {
        xf_c = __ldg(&xf[myc]);
        xh_c = __ldg(&xh[myc]);
    }
    // quota for split counter word `lane` (32 words):
    // #CTAs with (b & 31) == lane  =  ((NCTA - 1 - lane) >> 5) + 1
    const int quota = ((NCTA - 1 - lane) >> 5) + 1;

    // stage-duty: warp w (>=3) stages chunk w; warps 3,4,5 also chunks 0,1,2
    const int ch1 = (warp >= 3) ? warp : -1;
    const int ch2 = (warp >= 3 && warp <= 5) ? (warp - 3) : -1;

    float4* hsm4 = (float4*)hsm;
    hsm4[tid] = make_float4(0.f, 0.f, 0.f, 0.f);   // h_{-1} = 0
    __syncthreads();

    const ulonglong2* hp  = (const ulonglong2*)(hsm + warp * 128);  // 32 entries
    const ulonglong2* wsp = ws2 + warp * 256 + lane;

    for (int t = 0; t < T; t++) {
        // ---- 1. packed partial dot over this warp's k-chunk (hsm=h_{t-1}) --
        ull a0 = 0ULL, a1 = 0ULL;
        #pragma unroll
        for (int j = 0; j < 24; j++) {          // register half: k [0,96)
            ulonglong2 hv = hp[j];
            fma2(a0, hv.x, wr[2 * j + 0]);
            fma2(a1, hv.y, wr[2 * j + 1]);
        }
        #pragma unroll
        for (int jp = 0; jp < 8; jp++) {        // smem half: k [96,128)
            ulonglong2 hv = hp[24 + jp];
            ulonglong2 wv = wsp[jp * 32];
            fma2(a0, hv.x, wv.x);
            fma2(a1, hv.y, wv.y);
        }
        const float2 f0 = unpack2(a0);
        const float2 f1 = unpack2(a1);
        part[warp * 32 + lane] = (f0.x + f0.y) + (f1.x + f1.y);
        __syncthreads();   // (A) — partials ready; hsm free for restaging

        // ---- 3. phase 3: publish | arrive | detect | stage-next ----
        if (warp == 0) {
            float s = 0.f;
            #pragma unroll
            for (int w = 0; w < 16; w++) s += part[w * 32 + lane];
            const float partner = __shfl_sync(0xffffffffu, s, lane + np);
            const unsigned otag = ebase + (unsigned)t;
            if (lane < np) {
                const float pf = s + xf_c;
                const float ph = partner + xh_c;
                const float f  = 1.f / (1.f + __expf(-pf));
                float hn = f * hprev + (1.f - f) * tanhf(ph);
                hn = (hn >= 0.f) ? hn : a * hn;
                __stcg(&Hout[(size_t)t * H + myc], hn);
                st_tagged(&hx[(size_t)(t & 1) * H + myc],
                          ((ull)otag << 32) | (ull)__float_as_uint(hn));
                hprev = hn;
                if (t + 1 < T) {
                    xf_c = __ldg(&xf[(size_t)(t + 1) * H + myc]);
                    xh_c = __ldg(&xh[(size_t)(t + 1) * H + myc]);
                }
            }
        } else if (warp == 1) {
            if (lane == 0)
                atomicAdd(&ctr[t * 32 + (b & 31)], 1);   // advisory arrive
        } else if (warp == 2) {
            volatile int* p = ctr + t * 32 + lane;
            while (*p < quota) { }                       // detect (32 words)
        } else if (t + 1 < T) {
            // stage h_t chunks for step t+1 (bounded tag-poll)
            const ull* base = hx + (size_t)(t & 1) * H;
            const unsigned tag = ebase + (unsigned)t;
            #pragma unroll
            for (int c = 0; c < 2; c++) {
                const int ch = (c == 0) ? ch1 : ch2;
                if (ch < 0) continue;
                const ull* src = base + ch * 128 + lane * 4;
                ull v0 = ld_tagged(src + 0);
                ull v1 = ld_tagged(src + 1);
                ull v2 = ld_tagged(src + 2);
                ull v3 = ld_tagged(src + 3);
                while ((unsigned)(v0 >> 32) != tag || (unsigned)(v1 >> 32) != tag ||
                       (unsigned)(v2 >> 32) != tag || (unsigned)(v3 >> 32) != tag) {
                    if ((unsigned)(v0 >> 32) != tag) v0 = ld_tagged(src + 0);
                    if ((unsigned)(v1 >> 32) != tag) v1 = ld_tagged(src + 1);
                    if ((unsigned)(v2 >> 32) != tag) v2 = ld_tagged(src + 2);
                    if ((unsigned)(v3 >> 32) != tag) v3 = ld_tagged(src + 3);
                }
                float4 hv;
                hv.x = __uint_as_float((unsigned)v0);
                hv.y = __uint_as_float((unsigned)v1);
                hv.z = __uint_as_float((unsigned)v2);
                hv.w = __uint_as_float((unsigned)v3);
                hsm4[ch * 32 + lane] = hv;
            }
        }
        __syncthreads();   // (B) — staged, detected, published; release t+1
    }
}

// ---------------------------------------------------------------------------
// block reduce helper (256 threads)
// ---------------------------------------------------------------------------
__device__ __forceinline__ float block_sum_256(float v) {
    __shared__ float sh[8];
    const int tid = threadIdx.x;
    #pragma unroll
    for (int s = 16; s; s >>= 1) v += __shfl_xor_sync(0xffffffffu, v, s);
    if ((tid & 31) == 0) sh[tid >> 5] = v;
    __syncthreads();
    if (tid == 0) {
        float r = 0.f;
        #pragma unroll
        for (int i = 0; i < 8; i++) r += sh[i];
        sh[0] = r;
    }
    __syncthreads();
    const float r = sh[0];
    __syncthreads();
    return r;
}

// ---------------------------------------------------------------------------
// LayerNorm (torch-style: unbiased std). 1 row/block.
// ---------------------------------------------------------------------------
__global__ __launch_bounds__(256) void layernorm_kernel(
    const float* __restrict__ X, const float* __restrict__ ga,
    const float* __restrict__ be, float* __restrict__ Y)
{
    const int H = H_DIM;
    const int row = blockIdx.x;
    const int tid = threadIdx.x;
    const float* x = X + (size_t)row * H;
    float xr[8];
    #pragma unroll
    for (int j = 0; j < 8; j++) xr[j] = x[tid + 256 * j];

    float s = 0.f;
    #pragma unroll
    for (int j = 0; j < 8; j++) s += xr[j];
    const float mean = block_sum_256(s) * (1.f / H);

    float sq = 0.f;
    #pragma unroll
    for (int j = 0; j < 8; j++) { const float d = xr[j] - mean; sq += d * d; }
    const float var = block_sum_256(sq) * (1.f / (H - 1));
    const float inv = 1.f / (sqrtf(var) + EPS);

    float* y = Y + (size_t)row * H;
    #pragma unroll
    for (int j = 0; j < 8; j++) {
        const int k = tid + 256 * j;
        y[k] = ga[k] * (xr[j] - mean) * inv + be[k];
    }
}

// ---------------------------------------------------------------------------
// Fused head: LN(layer1 h) @ W_out + b_out -> log_softmax.  1 row/block.
// ---------------------------------------------------------------------------
__global__ __launch_bounds__(256) void head_kernel(
    const float* __restrict__ Hin, const float* __restrict__ ga,
    const float* __restrict__ be, const float* __restrict__ Wout,
    const float* __restrict__ bout, float* __restrict__ out)
{
    const int H = H_DIM;
    const int row = blockIdx.x;
    const int tid = threadIdx.x;
    const float* x = Hin + (size_t)row * H;

    float xr[8];
    #pragma unroll
    for (int j = 0; j < 8; j++) xr[j] = x[tid + 256 * j];

    float s = 0.f;
    #pragma unroll
    for (int j = 0; j < 8; j++) s += xr[j];
    const float mean = block_sum_256(s) * (1.f / H);

    float sq = 0.f;
    #pragma unroll
    for (int j = 0; j < 8; j++) { const float d = xr[j] - mean; sq += d * d; }
    const float var = block_sum_256(sq) * (1.f / (H - 1));
    const float inv = 1.f / (sqrtf(var) + EPS);

    float acc[OUT_DIM];
    #pragma unroll
    for (int o = 0; o < OUT_DIM; o++) acc[o] = 0.f;
    #pragma unroll
    for (int j = 0; j < 8; j++) {
        const int k = tid + 256 * j;
        const float xn = ga[k] * (xr[j] - mean) * inv + be[k];
        #pragma unroll
        for (int o = 0; o < OUT_DIM; o++)
            acc[o] = fmaf(xn, Wout[k * OUT_DIM + o], acc[o]);
    }

    __shared__ float wred[8][OUT_DIM];
    #pragma unroll
    for (int o = 0; o < OUT_DIM; o++) {
        float v = acc[o];
        #pragma unroll
        for (int st = 16; st; st >>= 1) v += __shfl_xor_sync(0xffffffffu, v, st);
        if ((tid & 31) == 0) wred[tid >> 5][o] = v;
    }
    __syncthreads();
    if (tid == 0) {
        float logits[OUT_DIM];
        #pragma unroll
        for (int o = 0; o < OUT_DIM; o++) {
            float v = bout[o];
            #pragma unroll
            for (int w = 0; w < 8; w++) v += wred[w][o];
            logits[o] = v;
        }
        float mx = logits[0];
        #pragma unroll
        for (int o = 1; o < OUT_DIM; o++) mx = fmaxf(mx, logits[o]);
        float se = 0.f;
        #pragma unroll
        for (int o = 0; o < OUT_DIM; o++) se += expf(logits[o] - mx);
        const float lse = mx + logf(se);
        #pragma unroll
        for (int o = 0; o < OUT_DIM; o++)
            out[(size_t)row * OUT_DIM + o] = logits[o] - lse;
    }
}

// ---------------------------------------------------------------------------
// Launch
// ---------------------------------------------------------------------------
extern "C" void kernel_launch(void* const* d_in, const int* in_sizes, int n_in,
                              void* d_out, int out_size)
{
    const float* x     = (const float*)d_in[0];
    const float* W_f0  = (const float*)d_in[1];
    const float* U_f0  = (const float*)d_in[2];
    const float* b_f0  = (const float*)d_in[3];
    const float* W_h0  = (const float*)d_in[4];
    const float* U_h0  = (const float*)d_in[5];
    const float* b_h0  = (const float*)d_in[6];
    const float* pr0   = (const float*)d_in[7];
    const float* ga0   = (const float*)d_in[8];
    const float* be0   = (const float*)d_in[9];
    const float* W_f1  = (const float*)d_in[10];
    const float* U_f1  = (const float*)d_in[11];
    const float* b_f1  = (const float*)d_in[12];
    const float* W_h1  = (const float*)d_in[13];
    const float* U_h1  = (const float*)d_in[14];
    const float* b_h1  = (const float*)d_in[15];
    const float* pr1   = (const float*)d_in[16];
    const float* ga1   = (const float*)d_in[17];
    const float* be1   = (const float*)d_in[18];
    const float* W_out = (const float*)d_in[19];
    const float* b_out = (const float*)d_in[20];
    float* out = (float*)d_out;

    const int H = H_DIM;
    const int T = in_sizes[0] / 2048;   // 4096

    float *p_xf, *p_xh, *p_h, *p_hn;
    ull* p_hx;
    int* p_ctr;
    cudaGetSymbolAddress((void**)&p_xf, g_xf);
    cudaGetSymbolAddress((void**)&p_xh, g_xh);
    cudaGetSymbolAddress((void**)&p_h,  g_h);
    cudaGetSymbolAddress((void**)&p_hn, g_hn);
    cudaGetSymbolAddress((void**)&p_hx, g_hx);
    cudaGetSymbolAddress((void**)&p_ctr, g_ctr);

    // actual use: 64KB weights + 8KB h + 2KB partials = 74KB.
    // Request 136KB to hard-force 1 CTA/SM (barrier needs all 148 resident).
    const int scan_smem = 136 * 1024;
    cudaFuncSetAttribute(janet_scan_kernel,
                         cudaFuncAttributeMaxDynamicSharedMemorySize, scan_smem);

    dim3 ggrid(H / 128, T / 128, 2);   // (16, 32, 2): f and h GEMMs fused

    // reset tags once (tag 0 matches no epoch; epochs are 1..2T)
    cudaMemsetAsync(p_hx, 0, 2 * H * sizeof(ull));

    // ---- layer 0 ----
    cudaMemsetAsync(p_ctr, 0, (size_t)T * 32 * sizeof(int));
    tf32_gemm_bias2_kernel<<<ggrid, 256>>>(x, W_f0, b_f0, p_xf, W_h0, b_h0, p_xh, T, H, H);
    janet_scan_kernel<<<NCTA, SCAN_THREADS, scan_smem>>>(
        U_f0, U_h0, p_xf, p_xh, p_h, pr0, p_hx, p_ctr, 1u, T);
    layernorm_kernel<<<T, 256>>>(p_h, ga0, be0, p_hn);

    // ---- layer 1 ----
    cudaMemsetAsync(p_ctr, 0, (size_t)T * 32 * sizeof(int));
    tf32_gemm_bias2_kernel<<<ggrid, 256>>>(p_hn, W_f1, b_f1, p_xf, W_h1, b_h1, p_xh, T, H, H);
    janet_scan_kernel<<<NCTA, SCAN_THREADS, scan_smem>>>(
        U_f1, U_h1, p_xf, p_xh, p_h, pr1, p_hx, p_ctr, 1u + (unsigned)T, T);

    // ---- LN1 + head + log_softmax ----
    head_kernel<<<T, 256>>>(p_h, ga1, be1, W_out, b_out, out);
}

// round 17
// speedup vs baseline: 2.0569x; 2.0569x over previous
#include <cuda_runtime.h>
#include <cuda_bf16.h>
#include <math.h>

// ---------------------------------------------------------------------------
// Problem constants
// ---------------------------------------------------------------------------
#define T_MAX 4096
#define H_DIM 2048
#define OUT_DIM 10
#define NCTA 148
#define SCAN_THREADS 512
#define EPS 1e-6f

typedef unsigned long long ull;

// packed fp32x2 helpers (PTX ISA 8.7+, sm_100+)
__device__ __forceinline__ void fma2(ull& acc, ull a, ull b) {
    asm("fma.rn.f32x2 %0, %1, %2, %0;" : "+l"(acc) : "l"(a), "l"(b));
}
__device__ __forceinline__ ull pack2(float x, float y) {
    ull r; asm("mov.b64 %0, {%1, %2};" : "=l"(r) : "f"(x), "f"(y)); return r;
}
__device__ __forceinline__ float2 unpack2(ull p) {
    float2 f; asm("mov.b64 {%0, %1}, %2;" : "=f"(f.x), "=f"(f.y) : "l"(p)); return f;
}

// tf32 helpers
__device__ __forceinline__ float totf32(float x) {
    float r; asm("cvt.rna.tf32.f32 %0, %1;" : "=f"(r) : "f"(x)); return r;
}
__device__ __forceinline__ void mma_tf32(float* c, const float* a, const float* b) {
    asm("mma.sync.aligned.m16n8k8.row.col.f32.tf32.tf32.f32 "
        "{%0,%1,%2,%3}, {%4,%5,%6,%7}, {%8,%9}, {%0,%1,%2,%3};"
        : "+f"(c[0]), "+f"(c[1]), "+f"(c[2]), "+f"(c[3])
        : "f"(a[0]), "f"(a[1]), "f"(a[2]), "f"(a[3]), "f"(b[0]), "f"(b[1]));
}

// tagged dataflow word: (epoch << 32) | float_bits. Relaxed gpu-scope ld/st;
// the tag rides with the value, so value visibility needs NO fences.
__device__ __forceinline__ void st_tagged(ull* p, ull v) {
    asm volatile("st.relaxed.gpu.global.u64 [%0], %1;" :: "l"(p), "l"(v) : "memory");
}
__device__ __forceinline__ ull ld_tagged(const ull* p) {
    ull v;
    asm volatile("ld.relaxed.gpu.global.u64 %0, [%1];" : "=l"(v) : "l"(p) : "memory");
    return v;
}

// scratch (device globals: allocation-free)
__device__ float g_xf[T_MAX * H_DIM];   // x @ W_f + b_f
__device__ float g_xh[T_MAX * H_DIM];   // x @ W_h + b_h
__device__ float g_h [T_MAX * H_DIM];   // scan output
__device__ float g_hn[T_MAX * H_DIM];   // layernorm output (layer 0)
__device__ ull   g_hx[4 * H_DIM];       // tagged h exchange (4-deep)
__device__ int   g_ctr[T_MAX * 32];     // split "staged" counters (32/step)

// ---------------------------------------------------------------------------
// TF32 tensor-core GEMM with bias, fused f/h pair (blockIdx.z selects).
// (unchanged: 154 TF/s measured, 0.45 ms/launch)
// ---------------------------------------------------------------------------
#define GBK 32
#define AS_STR 36
#define BS_STR 136

__global__ __launch_bounds__(256) void tf32_gemm_bias2_kernel(
    const float* __restrict__ A,
    const float* __restrict__ Bf, const float* __restrict__ biasf, float* __restrict__ Cf,
    const float* __restrict__ Bh, const float* __restrict__ biash, float* __restrict__ Ch,
    int M, int N, int K)
{
    __shared__ float As[128 * AS_STR];
    __shared__ float Bs[GBK * BS_STR];

    const float* B    = blockIdx.z ? Bh : Bf;
    const float* bias = blockIdx.z ? biash : biasf;
    float*       C    = blockIdx.z ? Ch : Cf;

    const int tid  = threadIdx.x;
    const int warp = tid >> 5;
    const int lane = tid & 31;
    const int g    = lane >> 2;
    const int tg   = lane & 3;

    const int wm = (warp >> 2) * 64;
    const int wn = (warp & 3) * 32;

    const int ar  = tid >> 3;
    const int ac4 = (tid & 7) * 4;
    const int br  = tid >> 5;
    const int bc4 = (tid & 31) * 4;

    float acc[4][4][4];
    #pragma unroll
    for (int mt = 0; mt < 4; mt++)
        #pragma unroll
        for (int nt = 0; nt < 4; nt++)
            #pragma unroll
            for (int r = 0; r < 4; r++) acc[mt][nt][r] = 0.f;

    const float* Ap = A + (size_t)(blockIdx.y * 128) * K;
    const float* Bp = B + blockIdx.x * 128;

    for (int kt = 0; kt < K; kt += GBK) {
        float4 a4[4], b4[4];
        #pragma unroll
        for (int i = 0; i < 4; i++)
            a4[i] = *(const float4*)(Ap + (size_t)(ar + 32 * i) * K + kt + ac4);
        #pragma unroll
        for (int i = 0; i < 4; i++)
            b4[i] = *(const float4*)(Bp + (size_t)(kt + br + 8 * i) * N + bc4);
        #pragma unroll
        for (int i = 0; i < 4; i++) {
            a4[i].x = totf32(a4[i].x); a4[i].y = totf32(a4[i].y);
            a4[i].z = totf32(a4[i].z); a4[i].w = totf32(a4[i].w);
            b4[i].x = totf32(b4[i].x); b4[i].y = totf32(b4[i].y);
            b4[i].z = totf32(b4[i].z); b4[i].w = totf32(b4[i].w);
        }
        __syncthreads();
        #pragma unroll
        for (int i = 0; i < 4; i++)
            *(float4*)&As[(ar + 32 * i) * AS_STR + ac4] = a4[i];
        #pragma unroll
        for (int i = 0; i < 4; i++)
            *(float4*)&Bs[(br + 8 * i) * BS_STR + bc4] = b4[i];
        __syncthreads();

        #pragma unroll
        for (int ks = 0; ks < 4; ks++) {
            const int kk = ks * 8;
            float af[4][4], bf[4][2];
            #pragma unroll
            for (int mt = 0; mt < 4; mt++) {
                const int m0 = wm + mt * 16;
                af[mt][0] = As[(m0 + g)     * AS_STR + kk + tg];
                af[mt][1] = As[(m0 + g + 8) * AS_STR + kk + tg];
                af[mt][2] = As[(m0 + g)     * AS_STR + kk + tg + 4];
                af[mt][3] = As[(m0 + g + 8) * AS_STR + kk + tg + 4];
            }
            #pragma unroll
            for (int nt = 0; nt < 4; nt++) {
                const int n0 = wn + nt * 8;
                bf[nt][0] = Bs[(kk + tg)     * BS_STR + n0 + g];
                bf[nt][1] = Bs[(kk + tg + 4) * BS_STR + n0 + g];
            }
            #pragma unroll
            for (int mt = 0; mt < 4; mt++)
                #pragma unroll
                for (int nt = 0; nt < 4; nt++)
                    mma_tf32(acc[mt][nt], af[mt], bf[nt]);
        }
    }

    #pragma unroll
    for (int mt = 0; mt < 4; mt++) {
        const int row0 = blockIdx.y * 128 + wm + mt * 16 + g;
        const int row1 = row0 + 8;
        #pragma unroll
        for (int nt = 0; nt < 4; nt++) {
            const int col = blockIdx.x * 128 + wn + nt * 8 + 2 * tg;
            const float b0 = bias[col], b1 = bias[col + 1];
            float2 v0, v1;
            v0.x = acc[mt][nt][0] + b0; v0.y = acc[mt][nt][1] + b1;
            v1.x = acc[mt][nt][2] + b0; v1.y = acc[mt][nt][3] + b1;
            *(float2*)(C + (size_t)row0 * N + col) = v0;
            *(float2*)(C + (size_t)row1 * N + col) = v1;
        }
    }
}

// ---------------------------------------------------------------------------
// Persistent JANET scan — R15 skeleton + 4-DEEP exchange + STALE detect.
// 148 CTAs x 512 threads (16 warps), 1 CTA/SM (smem-pinned, single wave).
//
// Step t:
//   1. stage own 128-col chunk of h_{t-1} from tagged slot (t-1)&3
//      (per-warp-own-chunk, selective re-read of mismatches only)
//   2. packed f32x2 partial dot -> part[] -> __syncthreads (A)
//      (sync A == "this CTA staged AND dotted h_{t-1}")
//   3. overlapped roles:
//        warp 0 : reduce partials, gate, __stcg Hout, st_tagged h_t -> slot t&3
//        warp 1 : atomicAdd ctr[t*32 + (b&31)]           (arrive: "staged h_{t-1}")
//        warp 2 : detect ctr[t-2] full (STALE — certifies all CTAs staged
//                 h_{t-3}; consumed by the publish at step t+1, whose slot
//                 (t+1)&3 previously held h_{t-3}). Two steps stale =>
//                 first-read hit; detect leaves the critical path and CTAs
//                 may slip up to 3 steps, absorbing per-step jitter.
//   4. __syncthreads (B)
// Slot safety: publish h_s (slot s&3, previously h_{s-4}) is ordered after
// syncB(s-1) which includes detect of ctr[s-3] = all CTAs staged+dotted
// h_{s-4}. For s<4 vacuous (slots start tag-0). Bounded slip <= 3 steps
// keeps value-poll traffic bounded (this is NOT the R7/R14 free-run mode).
// No fences anywhere: every word self-validates by its epoch tag.
// ---------------------------------------------------------------------------
__global__ __launch_bounds__(SCAN_THREADS, 1) void janet_scan_kernel(
    const float* __restrict__ Uf, const float* __restrict__ Uh,
    const float* __restrict__ xf, const float* __restrict__ xh,
    float* __restrict__ Hout, const float* __restrict__ prelu_a,
    ull* __restrict__ hx, int* __restrict__ ctr, unsigned ebase, int T)
{
    extern __shared__ float smem[];
    const int H = H_DIM;
    ulonglong2* ws2 = (ulonglong2*)smem;      // 16 warps * 8 * 32 * 16B = 64KB
    float* hsm  = smem + (64 * 1024 / 4);     // 2048 floats (8KB)
    float* part = hsm + H;                    // 512 floats (2KB)

    const int b = blockIdx.x;
    const int c0 = (b * H) / NCTA;
    const int c1 = ((b + 1) * H) / NCTA;
    const int np = c1 - c0;          // 13 or 14 column pairs
    const int nd = 2 * np;

    const int tid  = threadIdx.x;
    const int lane = tid & 31;
    const int warp = tid >> 5;
    const float a = *prelu_a;

    // ---- load this lane's weights: 96 floats in regs + 32 in smem ----
    const bool valid = lane < nd;
    const int col = c0 + (lane < np ? lane : (valid ? lane - np : 0));
    const float* U = (lane < np) ? Uf : Uh;
    const int kbase = warp * 128;

    ull wr[48];
    #pragma unroll
    for (int i = 0; i < 48; i++) {
        const float w0 = valid ? U[(size_t)(kbase + 2 * i + 0) * H + col] : 0.f;
        const float w1 = valid ? U[(size_t)(kbase + 2 * i + 1) * H + col] : 0.f;
        wr[i] = pack2(w0, w1);
    }
    #pragma unroll
    for (int jp = 0; jp < 8; jp++) {
        const int kk = kbase + 96 + 4 * jp;
        const float w0 = valid ? U[(size_t)(kk + 0) * H + col] : 0.f;
        const float w1 = valid ? U[(size_t)(kk + 1) * H + col] : 0.f;
        const float w2 = valid ? U[(size_t)(kk + 2) * H + col] : 0.f;
        const float w3 = valid ? U[(size_t)(kk + 3) * H + col] : 0.f;
        ulonglong2 wv; wv.x = pack2(w0, w1); wv.y = pack2(w2, w3);
        ws2[warp * 256 + jp * 32 + lane] = wv;
    }

    // per-dot thread state (warp 0, lane < np drives the gate math)
    float hprev = 0.f, xf_c = 0.f, xh_c = 0.f;
    const int myc = c0 + lane;
    if (warp == 0 && lane < np) {
        xf_c = __ldg(&xf[myc]);
        xh_c = __ldg(&xh[myc]);
    }
    // quota for split counter word `lane` (32 words):
    // #CTAs with (b & 31) == lane  =  ((NCTA - 1 - lane) >> 5) + 1
    const int quota = ((NCTA - 1 - lane) >> 5) + 1;
    __syncthreads();

    float4* hsm4 = (float4*)hsm;
    const ulonglong2* hp  = (const ulonglong2*)(hsm + warp * 128);  // 32 entries
    const ulonglong2* wsp = ws2 + warp * 256 + lane;

    for (int t = 0; t < T; t++) {
        // ---- 1. stage own chunk of h_{t-1} from slot (t-1)&3 ----
        if (t == 0) {
            hsm4[tid] = make_float4(0.f, 0.f, 0.f, 0.f);
        } else {
            const ull* src = hx + (size_t)((t - 1) & 3) * H + warp * 128 + lane * 4;
            const unsigned tag = ebase + (unsigned)(t - 1);
            ull v0 = ld_tagged(src + 0);
            ull v1 = ld_tagged(src + 1);
            ull v2 = ld_tagged(src + 2);
            ull v3 = ld_tagged(src + 3);
            while ((unsigned)(v0 >> 32) != tag || (unsigned)(v1 >> 32) != tag ||
                   (unsigned)(v2 >> 32) != tag || (unsigned)(v3 >> 32) != tag) {
                if ((unsigned)(v0 >> 32) != tag) v0 = ld_tagged(src + 0);
                if ((unsigned)(v1 >> 32) != tag) v1 = ld_tagged(src + 1);
                if ((unsigned)(v2 >> 32) != tag) v2 = ld_tagged(src + 2);
                if ((unsigned)(v3 >> 32) != tag) v3 = ld_tagged(src + 3);
            }
            float4 hv;
            hv.x = __uint_as_float((unsigned)v0);
            hv.y = __uint_as_float((unsigned)v1);
            hv.z = __uint_as_float((unsigned)v2);
            hv.w = __uint_as_float((unsigned)v3);
            hsm4[tid] = hv;
        }
        __syncwarp();

        // ---- 2. packed partial dot over this warp's k-chunk ----
        ull a0 = 0ULL, a1 = 0ULL;
        #pragma unroll
        for (int j = 0; j < 24; j++) {          // register half: k [0,96)
            ulonglong2 hv = hp[j];
            fma2(a0, hv.x, wr[2 * j + 0]);
            fma2(a1, hv.y, wr[2 * j + 1]);
        }
        #pragma unroll
        for (int jp = 0; jp < 8; jp++) {        // smem half: k [96,128)
            ulonglong2 hv = hp[24 + jp];
            ulonglong2 wv = wsp[jp * 32];
            fma2(a0, hv.x, wv.x);
            fma2(a1, hv.y, wv.y);
        }
        const float2 f0 = unpack2(a0);
        const float2 f1 = unpack2(a1);
        part[warp * 32 + lane] = (f0.x + f0.y) + (f1.x + f1.y);
        __syncthreads();   // (A) — staged + dotted h_{t-1}

        // ---- 3. overlapped: publish | arrive | stale-detect ----
        if (warp == 0) {
            float s = 0.f;
            #pragma unroll
            for (int w = 0; w < 16; w++) s += part[w * 32 + lane];
            const float partner = __shfl_sync(0xffffffffu, s, lane + np);
            const unsigned otag = ebase + (unsigned)t;
            if (lane < np) {
                const float pf = s + xf_c;
                const float ph = partner + xh_c;
                const float f  = 1.f / (1.f + __expf(-pf));
                float hn = f * hprev + (1.f - f) * tanhf(ph);
                hn = (hn >= 0.f) ? hn : a * hn;
                __stcg(&Hout[(size_t)t * H + myc], hn);
                st_tagged(&hx[(size_t)(t & 3) * H + myc],
                          ((ull)otag << 32) | (ull)__float_as_uint(hn));
                hprev = hn;
                if (t + 1 < T) {
                    xf_c = __ldg(&xf[(size_t)(t + 1) * H + myc]);
                    xh_c = __ldg(&xh[(size_t)(t + 1) * H + myc]);
                }
            }
        } else if (warp == 1) {
            if (lane == 0)
                atomicAdd(&ctr[t * 32 + (b & 31)], 1);   // arrive: staged h_{t-1}
        } else if (warp == 2) {
            if (t >= 2) {
                volatile int* p = ctr + (t - 2) * 32 + lane;
                while (*p < quota) { }     // stale detect: ~always first-read hit
            }
        }
        __syncthreads();   // (B) — release t+1
    }
}

// ---------------------------------------------------------------------------
// block reduce helper (256 threads)
// ---------------------------------------------------------------------------
__device__ __forceinline__ float block_sum_256(float v) {
    __shared__ float sh[8];
    const int tid = threadIdx.x;
    #pragma unroll
    for (int s = 16; s; s >>= 1) v += __shfl_xor_sync(0xffffffffu, v, s);
    if ((tid & 31) == 0) sh[tid >> 5] = v;
    __syncthreads();
    if (tid == 0) {
        float r = 0.f;
        #pragma unroll
        for (int i = 0; i < 8; i++) r += sh[i];
        sh[0] = r;
    }
    __syncthreads();
    const float r = sh[0];
    __syncthreads();
    return r;
}

// ---------------------------------------------------------------------------
// LayerNorm (torch-style: unbiased std). 1 row/block.
// ---------------------------------------------------------------------------
__global__ __launch_bounds__(256) void layernorm_kernel(
    const float* __restrict__ X, const float* __restrict__ ga,
    const float* __restrict__ be, float* __restrict__ Y)
{
    const int H = H_DIM;
    const int row = blockIdx.x;
    const int tid = threadIdx.x;
    const float* x = X + (size_t)row * H;
    float xr[8];
    #pragma unroll
    for (int j = 0; j < 8; j++) xr[j] = x[tid + 256 * j];

    float s = 0.f;
    #pragma unroll
    for (int j = 0; j < 8; j++) s += xr[j];
    const float mean = block_sum_256(s) * (1.f / H);

    float sq = 0.f;
    #pragma unroll
    for (int j = 0; j < 8; j++) { const float d = xr[j] - mean; sq += d * d; }
    const float var = block_sum_256(sq) * (1.f / (H - 1));
    const float inv = 1.f / (sqrtf(var) + EPS);

    float* y = Y + (size_t)row * H;
    #pragma unroll
    for (int j = 0; j < 8; j++) {
        const int k = tid + 256 * j;
        y[k] = ga[k] * (xr[j] - mean) * inv + be[k];
    }
}

// ---------------------------------------------------------------------------
// Fused head: LN(layer1 h) @ W_out + b_out -> log_softmax.  1 row/block.
// ---------------------------------------------------------------------------
__global__ __launch_bounds__(256) void head_kernel(
    const float* __restrict__ Hin, const float* __restrict__ ga,
    const float* __restrict__ be, const float* __restrict__ Wout,
    const float* __restrict__ bout, float* __restrict__ out)
{
    const int H = H_DIM;
    const int row = blockIdx.x;
    const int tid = threadIdx.x;
    const float* x = Hin + (size_t)row * H;

    float xr[8];
    #pragma unroll
    for (int j = 0; j < 8; j++) xr[j] = x[tid + 256 * j];

    float s = 0.f;
    #pragma unroll
    for (int j = 0; j < 8; j++) s += xr[j];
    const float mean = block_sum_256(s) * (1.f / H);

    float sq = 0.f;
    #pragma unroll
    for (int j = 0; j < 8; j++) { const float d = xr[j] - mean; sq += d * d; }
    const float var = block_sum_256(sq) * (1.f / (H - 1));
    const float inv = 1.f / (sqrtf(var) + EPS);

    float acc[OUT_DIM];
    #pragma unroll
    for (int o = 0; o < OUT_DIM; o++) acc[o] = 0.f;
    #pragma unroll
    for (int j = 0; j < 8; j++) {
        const int k = tid + 256 * j;
        const float xn = ga[k] * (xr[j] - mean) * inv + be[k];
        #pragma unroll
        for (int o = 0; o < OUT_DIM; o++)
            acc[o] = fmaf(xn, Wout[k * OUT_DIM + o], acc[o]);
    }

    __shared__ float wred[8][OUT_DIM];
    #pragma unroll
    for (int o = 0; o < OUT_DIM; o++) {
        float v = acc[o];
        #pragma unroll
        for (int st = 16; st; st >>= 1) v += __shfl_xor_sync(0xffffffffu, v, st);
        if ((tid & 31) == 0) wred[tid >> 5][o] = v;
    }
    __syncthreads();
    if (tid == 0) {
        float logits[OUT_DIM];
        #pragma unroll
        for (int o = 0; o < OUT_DIM; o++) {
            float v = bout[o];
            #pragma unroll
            for (int w = 0; w < 8; w++) v += wred[w][o];
            logits[o] = v;
        }
        float mx = logits[0];
        #pragma unroll
        for (int o = 1; o < OUT_DIM; o++) mx = fmaxf(mx, logits[o]);
        float se = 0.f;
        #pragma unroll
        for (int o = 0; o < OUT_DIM; o++) se += expf(logits[o] - mx);
        const float lse = mx + logf(se);
        #pragma unroll
        for (int o = 0; o < OUT_DIM; o++)
            out[(size_t)row * OUT_DIM + o] = logits[o] - lse;
    }
}

// ---------------------------------------------------------------------------
// Launch
// ---------------------------------------------------------------------------
extern "C" void kernel_launch(void* const* d_in, const int* in_sizes, int n_in,
                              void* d_out, int out_size)
{
    const float* x     = (const float*)d_in[0];
    const float* W_f0  = (const float*)d_in[1];
    const float* U_f0  = (const float*)d_in[2];
    const float* b_f0  = (const float*)d_in[3];
    const float* W_h0  = (const float*)d_in[4];
    const float* U_h0  = (const float*)d_in[5];
    const float* b_h0  = (const float*)d_in[6];
    const float* pr0   = (const float*)d_in[7];
    const float* ga0   = (const float*)d_in[8];
    const float* be0   = (const float*)d_in[9];
    const float* W_f1  = (const float*)d_in[10];
    const float* U_f1  = (const float*)d_in[11];
    const float* b_f1  = (const float*)d_in[12];
    const float* W_h1  = (const float*)d_in[13];
    const float* U_h1  = (const float*)d_in[14];
    const float* b_h1  = (const float*)d_in[15];
    const float* pr1   = (const float*)d_in[16];
    const float* ga1   = (const float*)d_in[17];
    const float* be1   = (const float*)d_in[18];
    const float* W_out = (const float*)d_in[19];
    const float* b_out = (const float*)d_in[20];
    float* out = (float*)d_out;

    const int H = H_DIM;
    const int T = in_sizes[0] / 2048;   // 4096

    float *p_xf, *p_xh, *p_h, *p_hn;
    ull* p_hx;
    int* p_ctr;
    cudaGetSymbolAddress((void**)&p_xf, g_xf);
    cudaGetSymbolAddress((void**)&p_xh, g_xh);
    cudaGetSymbolAddress((void**)&p_h,  g_h);
    cudaGetSymbolAddress((void**)&p_hn, g_hn);
    cudaGetSymbolAddress((void**)&p_hx, g_hx);
    cudaGetSymbolAddress((void**)&p_ctr, g_ctr);

    // actual use: 64KB weights + 8KB h + 2KB partials = 74KB.
    // Request 136KB to hard-force 1 CTA/SM (barrier needs all 148 resident).
    const int scan_smem = 136 * 1024;
    cudaFuncSetAttribute(janet_scan_kernel,
                         cudaFuncAttributeMaxDynamicSharedMemorySize, scan_smem);

    dim3 ggrid(H / 128, T / 128, 2);   // (16, 32, 2): f and h GEMMs fused

    // reset tags once (tag 0 matches no epoch; epochs are 1..2T)
    cudaMemsetAsync(p_hx, 0, 4 * H * sizeof(ull));

    // ---- layer 0 ----
    cudaMemsetAsync(p_ctr, 0, (size_t)T * 32 * sizeof(int));
    tf32_gemm_bias2_kernel<<<ggrid, 256>>>(x, W_f0, b_f0, p_xf, W_h0, b_h0, p_xh, T, H, H);
    janet_scan_kernel<<<NCTA, SCAN_THREADS, scan_smem>>>(
        U_f0, U_h0, p_xf, p_xh, p_h, pr0, p_hx, p_ctr, 1u, T);
    layernorm_kernel<<<T, 256>>>(p_h, ga0, be0, p_hn);

    // ---- layer 1 ----
    cudaMemsetAsync(p_ctr, 0, (size_t)T * 32 * sizeof(int));
    tf32_gemm_bias2_kernel<<<ggrid, 256>>>(p_hn, W_f1, b_f1, p_xf, W_h1, b_h1, p_xh, T, H, H);
    janet_scan_kernel<<<NCTA, SCAN_THREADS, scan_smem>>>(
        U_f1, U_h1, p_xf, p_xh, p_h, pr1, p_hx, p_ctr, 1u + (unsigned)T, T);

    // ---- LN1 + head + log_softmax ----
    head_kernel<<<T, 256>>>(p_h, ga1, be1, W_out, b_out, out);
}